// round 2
// baseline (speedup 1.0000x reference)
#include <cuda_runtime.h>
#include <cstdint>

#define EMB 128
#define NMAX 50000
#define EMAX 800000

// ---------------- scratch (static device globals; no allocation) ----------------
__device__ float g_aggr[NMAX * EMB];          // 25.6 MB
__device__ float g_h1[NMAX * 2 * EMB];        // 51.2 MB
__device__ float g_stat[768];                 // sum1[256] sq1[256] sum2[128] sq2[128]
__device__ float g_scale1[2 * EMB], g_shift1[2 * EMB];
__device__ float g_scale2[EMB],     g_shift2[EMB];
__device__ int   g_is64;
__device__ int   g_deg[NMAX];
__device__ int   g_off[NMAX + 1];
__device__ int   g_cur[NMAX];
__device__ uint2 g_elist[EMAX];               // (src, edge_id) sorted by dst

// ---------------- zero counters + stats each replay ------------------------------
__global__ void zero_kernel(int n) {
    int i = blockIdx.x * blockDim.x + threadIdx.x;
    if (i < n) g_deg[i] = 0;
    if (blockIdx.x == 0) {
        for (int j = threadIdx.x; j < 768; j += blockDim.x) g_stat[j] = 0.0f;
    }
}

// ---------------- detect edge_index dtype (int64 vs silently-downcast int32) ----
__global__ void detect_kernel(const unsigned long long* __restrict__ p, int n_nodes) {
    if (threadIdx.x == 0) {
        int ok = 1;
        for (int i = 0; i < 64; i++)
            if (p[i] >= (unsigned long long)n_nodes) { ok = 0; break; }
        g_is64 = ok;
    }
}

__device__ __forceinline__ void load_edge(const void* eiv, int e, int E,
                                          int& src, int& dst) {
    if (g_is64) {
        const long long* pe = (const long long*)eiv;
        src = (int)pe[e]; dst = (int)pe[(size_t)E + e];
    } else {
        const int* pe = (const int*)eiv;
        src = pe[e]; dst = pe[(size_t)E + e];
    }
}

// ---------------- CSR build: histogram ------------------------------------------
__global__ void hist_kernel(const void* __restrict__ eiv, int E) {
    int e = blockIdx.x * blockDim.x + threadIdx.x;
    if (e >= E) return;
    int src, dst; load_edge(eiv, e, E, src, dst);
    atomicAdd(&g_deg[dst], 1);
}

// ---------------- CSR build: single-block exclusive scan -------------------------
__global__ void scan_kernel(int n) {
    __shared__ int s[1024];
    __shared__ int carry_s;
    int tid = threadIdx.x;
    if (tid == 0) carry_s = 0;
    __syncthreads();
    for (int base = 0; base < n; base += 1024) {
        int v = (base + tid < n) ? g_deg[base + tid] : 0;
        s[tid] = v;
        __syncthreads();
        int x = v;
        for (int off = 1; off < 1024; off <<= 1) {
            int t = (tid >= off) ? s[tid - off] : 0;
            __syncthreads();
            x += t;
            s[tid] = x;
            __syncthreads();
        }
        int carry = carry_s;                 // stable: unchanged since last sync
        int excl = x - v + carry;
        if (base + tid < n) { g_off[base + tid] = excl; g_cur[base + tid] = excl; }
        __syncthreads();
        if (tid == 1023) carry_s = carry + x;
        __syncthreads();
    }
    if (tid == 0) g_off[n] = carry_s;
}

// ---------------- CSR build: scatter (src, e) by dst ------------------------------
__global__ void scatter_kernel(const void* __restrict__ eiv, int E) {
    int e = blockIdx.x * blockDim.x + threadIdx.x;
    if (e >= E) return;
    int src, dst; load_edge(eiv, e, E, src, dst);
    int pos = atomicAdd(&g_cur[dst], 1);
    g_elist[pos] = make_uint2((unsigned)src, (unsigned)e);
}

// ---------------- aggregation: 1 warp = 1 dst node --------------------------------
__global__ __launch_bounds__(256) void aggr_kernel(
    const float4* __restrict__ x4, const float* __restrict__ ea,
    const float4* __restrict__ We4, const float4* __restrict__ be4, int n)
{
    __shared__ float4 sW[512];  // W_edge: 16 x 128 floats
    __shared__ float4 sB[32];   // b_edge
    int t = threadIdx.x;
    sW[t]       = We4[t];
    sW[t + 256] = We4[t + 256];
    if (t < 32) sB[t] = be4[t];
    __syncthreads();

    int lane = t & 31;
    int dst = blockIdx.x * 8 + (t >> 5);
    if (dst >= n) return;

    int beg = g_off[dst], end = g_off[dst + 1];
    float4 acc = make_float4(0.f, 0.f, 0.f, 0.f);
    const unsigned FULL = 0xffffffffu;

    for (int b = beg; b < end; b += 32) {
        int cnt = min(32, end - b);
        uint2 se = (lane < cnt) ? g_elist[b + lane] : make_uint2(0u, 0u);
        // prefetch this lane's edge_attr row (16 floats) — full MLP across 32 edges
        float av[16];
        if (lane < cnt) {
            const float4* pa = (const float4*)(ea + (size_t)se.y * 16);
            float4 a0 = pa[0], a1 = pa[1], a2 = pa[2], a3 = pa[3];
            av[0]=a0.x; av[1]=a0.y; av[2]=a0.z; av[3]=a0.w;
            av[4]=a1.x; av[5]=a1.y; av[6]=a1.z; av[7]=a1.w;
            av[8]=a2.x; av[9]=a2.y; av[10]=a2.z; av[11]=a2.w;
            av[12]=a3.x; av[13]=a3.y; av[14]=a3.z; av[15]=a3.w;
        } else {
#pragma unroll
            for (int k = 0; k < 16; k++) av[k] = 0.f;
        }
        for (int j = 0; j < cnt; j++) {
            int srcj = __shfl_sync(FULL, (int)se.x, j);
            float4 m = sB[lane];
#pragma unroll
            for (int k = 0; k < 16; k++) {
                float v = __shfl_sync(FULL, av[k], j);
                float4 w = sW[k * 32 + lane];
                m.x = fmaf(v, w.x, m.x);
                m.y = fmaf(v, w.y, m.y);
                m.z = fmaf(v, w.z, m.z);
                m.w = fmaf(v, w.w, m.w);
            }
            float4 xv = x4[(size_t)srcj * 32 + lane];
            acc.x += fmaxf(m.x + xv.x, 0.0f);
            acc.y += fmaxf(m.y + xv.y, 0.0f);
            acc.z += fmaxf(m.z + xv.z, 0.0f);
            acc.w += fmaxf(m.w + xv.w, 0.0f);
        }
    }
    *(float4*)(g_aggr + (size_t)dst * EMB + lane * 4) = acc;
}

// ---------------- GEMM1: h1 = ((1+eps)*x + aggr) @ W1 + b1  (M x 256, K=128) ----
__global__ __launch_bounds__(256, 2) void gemm1_kernel(
    const float* __restrict__ X, const float* __restrict__ W,
    const float* __restrict__ bias, const float* __restrict__ epsp, int M)
{
    __shared__ float As[16][132];
    __shared__ float Bs[16][132];
    const float eps1 = 1.0f + *epsp;
    int t = threadIdx.x;
    int tx = t & 15, ty = t >> 4;
    int row0 = blockIdx.x * 128;
    int col0 = blockIdx.y * 128;
    float acc[8][8] = {};

    for (int kt = 0; kt < 128; kt += 16) {
#pragma unroll
        for (int l = 0; l < 2; l++) {
            int f = t + l * 256;
            int r = f >> 2, kq = (f & 3) * 4;
            int m = row0 + r;
            float4 v = make_float4(0.f, 0.f, 0.f, 0.f);
            if (m < M) {
                float4 xv = *(const float4*)(X + (size_t)m * 128 + kt + kq);
                float4 av = *(const float4*)(g_aggr + (size_t)m * 128 + kt + kq);
                v.x = fmaf(eps1, xv.x, av.x);
                v.y = fmaf(eps1, xv.y, av.y);
                v.z = fmaf(eps1, xv.z, av.z);
                v.w = fmaf(eps1, xv.w, av.w);
            }
            As[kq + 0][r] = v.x; As[kq + 1][r] = v.y;
            As[kq + 2][r] = v.z; As[kq + 3][r] = v.w;
        }
#pragma unroll
        for (int l = 0; l < 2; l++) {
            int f = t + l * 256;
            int kr = f >> 5, nc = (f & 31) * 4;
            *(float4*)&Bs[kr][nc] =
                *(const float4*)(W + (size_t)(kt + kr) * 256 + col0 + nc);
        }
        __syncthreads();
#pragma unroll
        for (int kk = 0; kk < 16; kk++) {
            float a0[8], b0[8];
            *(float4*)(a0)     = *(const float4*)&As[kk][ty * 4];
            *(float4*)(a0 + 4) = *(const float4*)&As[kk][64 + ty * 4];
            *(float4*)(b0)     = *(const float4*)&Bs[kk][tx * 4];
            *(float4*)(b0 + 4) = *(const float4*)&Bs[kk][64 + tx * 4];
#pragma unroll
            for (int i = 0; i < 8; i++)
#pragma unroll
                for (int j = 0; j < 8; j++)
                    acc[i][j] = fmaf(a0[i], b0[j], acc[i][j]);
        }
        __syncthreads();
    }
#pragma unroll
    for (int i = 0; i < 8; i++) {
        int m = row0 + ((i < 4) ? (ty * 4 + i) : (64 + ty * 4 + i - 4));
        if (m >= M) continue;
#pragma unroll
        for (int h = 0; h < 2; h++) {
            int c = col0 + h * 64 + tx * 4;
            float4 bb = *(const float4*)(bias + c);
            float4 o;
            o.x = acc[i][h * 4 + 0] + bb.x;
            o.y = acc[i][h * 4 + 1] + bb.y;
            o.z = acc[i][h * 4 + 2] + bb.z;
            o.w = acc[i][h * 4 + 3] + bb.w;
            *(float4*)(g_h1 + (size_t)m * 256 + c) = o;
        }
    }
}

// ---------------- column stats for h1 (256 cols) ---------------------------------
__global__ void stats1_kernel(int M) {
    int col = threadIdx.x;  // 256
    int r0 = blockIdx.x * 256;
    int r1 = min(r0 + 256, M);
    float s = 0.f, q = 0.f;
    for (int r = r0; r < r1; r++) {
        float v = g_h1[(size_t)r * 256 + col];
        s += v; q = fmaf(v, v, q);
    }
    atomicAdd(&g_stat[col], s);
    atomicAdd(&g_stat[256 + col], q);
}

// ---------------- column stats for h2 (128 cols, reads d_out) --------------------
__global__ void stats2_kernel(const float* __restrict__ H, int M) {
    int col = threadIdx.x;  // 128
    int r0 = blockIdx.x * 256;
    int r1 = min(r0 + 256, M);
    float s = 0.f, q = 0.f;
    for (int r = r0; r < r1; r++) {
        float v = H[(size_t)r * 128 + col];
        s += v; q = fmaf(v, v, q);
    }
    atomicAdd(&g_stat[512 + col], s);
    atomicAdd(&g_stat[640 + col], q);
}

// ---------------- finalize BN stats into fused scale/shift -----------------------
__global__ void finalize_kernel(const float* __restrict__ gam,
                                const float* __restrict__ bet,
                                int which, float invM)
{
    int c = threadIdx.x;
    float mu, msq;
    if (which == 0) { mu = g_stat[c] * invM;       msq = g_stat[256 + c] * invM; }
    else            { mu = g_stat[512 + c] * invM; msq = g_stat[640 + c] * invM; }
    float var = msq - mu * mu;
    float sc = gam[c] * rsqrtf(var + 1e-5f);
    float sh = bet[c] - mu * sc;
    if (which == 0) { g_scale1[c] = sc; g_shift1[c] = sh; }
    else            { g_scale2[c] = sc; g_shift2[c] = sh; }
}

// ---------------- GEMM2: out = relu(BN1(h1)) @ W2 + b2  (M x 128, K=256) ---------
__global__ __launch_bounds__(256, 2) void gemm2_kernel(
    const float* __restrict__ W, const float* __restrict__ bias,
    float* __restrict__ out, int M)
{
    __shared__ float As[16][132];
    __shared__ float Bs[16][132];
    int t = threadIdx.x;
    int tx = t & 15, ty = t >> 4;
    int row0 = blockIdx.x * 128;
    float acc[8][8] = {};

    for (int kt = 0; kt < 256; kt += 16) {
#pragma unroll
        for (int l = 0; l < 2; l++) {
            int f = t + l * 256;
            int r = f >> 2, kq = (f & 3) * 4;
            int m = row0 + r;
            float4 v = make_float4(0.f, 0.f, 0.f, 0.f);
            if (m < M) {
                float4 hv = *(const float4*)(g_h1 + (size_t)m * 256 + kt + kq);
                float4 sc = *(const float4*)(g_scale1 + kt + kq);
                float4 sh = *(const float4*)(g_shift1 + kt + kq);
                v.x = fmaxf(fmaf(hv.x, sc.x, sh.x), 0.0f);
                v.y = fmaxf(fmaf(hv.y, sc.y, sh.y), 0.0f);
                v.z = fmaxf(fmaf(hv.z, sc.z, sh.z), 0.0f);
                v.w = fmaxf(fmaf(hv.w, sc.w, sh.w), 0.0f);
            }
            As[kq + 0][r] = v.x; As[kq + 1][r] = v.y;
            As[kq + 2][r] = v.z; As[kq + 3][r] = v.w;
        }
#pragma unroll
        for (int l = 0; l < 2; l++) {
            int f = t + l * 256;
            int kr = f >> 5, nc = (f & 31) * 4;
            *(float4*)&Bs[kr][nc] =
                *(const float4*)(W + (size_t)(kt + kr) * 128 + nc);
        }
        __syncthreads();
#pragma unroll
        for (int kk = 0; kk < 16; kk++) {
            float a0[8], b0[8];
            *(float4*)(a0)     = *(const float4*)&As[kk][ty * 4];
            *(float4*)(a0 + 4) = *(const float4*)&As[kk][64 + ty * 4];
            *(float4*)(b0)     = *(const float4*)&Bs[kk][tx * 4];
            *(float4*)(b0 + 4) = *(const float4*)&Bs[kk][64 + tx * 4];
#pragma unroll
            for (int i = 0; i < 8; i++)
#pragma unroll
                for (int j = 0; j < 8; j++)
                    acc[i][j] = fmaf(a0[i], b0[j], acc[i][j]);
        }
        __syncthreads();
    }
#pragma unroll
    for (int i = 0; i < 8; i++) {
        int m = row0 + ((i < 4) ? (ty * 4 + i) : (64 + ty * 4 + i - 4));
        if (m >= M) continue;
#pragma unroll
        for (int h = 0; h < 2; h++) {
            int c = h * 64 + tx * 4;
            float4 bb = *(const float4*)(bias + c);
            float4 o;
            o.x = acc[i][h * 4 + 0] + bb.x;
            o.y = acc[i][h * 4 + 1] + bb.y;
            o.z = acc[i][h * 4 + 2] + bb.z;
            o.w = acc[i][h * 4 + 3] + bb.w;
            *(float4*)(out + (size_t)m * 128 + c) = o;
        }
    }
}

// ---------------- Threefry-2x32, key = (0, 42) -----------------------------------
__device__ __forceinline__ uint2 threefry2x32_042(uint32_t x0, uint32_t x1)
{
    const uint32_t k0 = 0u, k1 = 42u;
    const uint32_t k2 = k0 ^ k1 ^ 0x1BD11BDAu;
    x0 += k0; x1 += k1;
#define TF_R(r) { x0 += x1; x1 = __funnelshift_l(x1, x1, r); x1 ^= x0; }
    TF_R(13) TF_R(15) TF_R(26) TF_R(6)
    x0 += k1; x1 += k2 + 1u;
    TF_R(17) TF_R(29) TF_R(16) TF_R(24)
    x0 += k2; x1 += k0 + 2u;
    TF_R(13) TF_R(15) TF_R(26) TF_R(6)
    x0 += k0; x1 += k1 + 3u;
    TF_R(17) TF_R(29) TF_R(16) TF_R(24)
    x0 += k1; x1 += k2 + 4u;
    TF_R(13) TF_R(15) TF_R(26) TF_R(6)
    x0 += k2; x1 += k0 + 5u;
#undef TF_R
    return make_uint2(x0, x1);
}

// ---------------- outer BN + dropout (JAX partitionable threefry) ----------------
__global__ void bn_dropout_kernel(float* __restrict__ out, int total)
{
    int t = blockIdx.x * blockDim.x + threadIdx.x;
    int i0 = t * 4;
    if (i0 >= total) return;
    float4 v = *(float4*)(out + i0);
    int c = i0 & 127;
    float4 sc = *(const float4*)(g_scale2 + c);
    float4 sh = *(const float4*)(g_shift2 + c);
    float vals[4] = { fmaf(v.x, sc.x, sh.x), fmaf(v.y, sc.y, sh.y),
                      fmaf(v.z, sc.z, sh.z), fmaf(v.w, sc.w, sh.w) };
    float res[4];
#pragma unroll
    for (int j = 0; j < 4; j++) {
        uint2 o = threefry2x32_042(0u, (uint32_t)(i0 + j));
        uint32_t bits = o.x ^ o.y;
        float u = __uint_as_float((bits >> 9) | 0x3f800000u) - 1.0f;
        res[j] = (u < 0.8f) ? vals[j] * 1.25f : 0.0f;
    }
    *(float4*)(out + i0) = make_float4(res[0], res[1], res[2], res[3]);
}

// ---------------- launch ----------------------------------------------------------
extern "C" void kernel_launch(void* const* d_in, const int* in_sizes, int n_in,
                              void* d_out, int out_size)
{
    const float* x      = (const float*)d_in[0];
    const void*  ei     = d_in[1];
    const float* ea     = (const float*)d_in[2];
    const float* W_edge = (const float*)d_in[3];
    const float* b_edge = (const float*)d_in[4];
    const float* epsp   = (const float*)d_in[5];
    const float* W1     = (const float*)d_in[6];
    const float* b1     = (const float*)d_in[7];
    const float* g1     = (const float*)d_in[8];
    const float* beta1  = (const float*)d_in[9];
    const float* W2     = (const float*)d_in[10];
    const float* b2     = (const float*)d_in[11];
    const float* g_o    = (const float*)d_in[12];
    const float* beta_o = (const float*)d_in[13];
    float* out = (float*)d_out;

    int M = in_sizes[0] / EMB;     // 50000
    int E = in_sizes[1] / 2;       // 800000
    float invM = 1.0f / (float)M;

    zero_kernel<<<(M + 255) / 256, 256>>>(M);
    detect_kernel<<<1, 1>>>((const unsigned long long*)ei, M);
    hist_kernel<<<(E + 255) / 256, 256>>>(ei, E);
    scan_kernel<<<1, 1024>>>(M);
    scatter_kernel<<<(E + 255) / 256, 256>>>(ei, E);
    aggr_kernel<<<(M + 7) / 8, 256>>>((const float4*)x, ea,
                                      (const float4*)W_edge, (const float4*)b_edge, M);
    int gM = (M + 127) / 128;
    gemm1_kernel<<<dim3(gM, 2), 256>>>(x, W1, b1, epsp, M);
    stats1_kernel<<<(M + 255) / 256, 256>>>(M);
    finalize_kernel<<<1, 256>>>(g1, beta1, 0, invM);
    gemm2_kernel<<<dim3(gM, 1), 256>>>(W2, b2, out, M);
    stats2_kernel<<<(M + 255) / 256, 128>>>(out, M);
    finalize_kernel<<<1, 128>>>(g_o, beta_o, 1, invM);
    bn_dropout_kernel<<<(out_size / 4 + 255) / 256, 256>>>(out, out_size);
}

// round 3
// speedup vs baseline: 1.1114x; 1.1114x over previous
#include <cuda_runtime.h>
#include <cstdint>

#define EMB 128
#define NMAX 50000
#define EMAX 800000
#define SCAN_B 1024
#define FULLM 0xffffffffu

// ---------------- scratch (static device globals; no allocation) ----------------
__device__ float g_aggr[NMAX * EMB];          // 25.6 MB
__device__ float g_h1[NMAX * 2 * EMB];        // 51.2 MB
__device__ float g_stat[768];                 // sum1[256] sq1[256] sum2[128] sq2[128]
__device__ float g_scale1[2 * EMB], g_shift1[2 * EMB];
__device__ float g_scale2[EMB],     g_shift2[EMB];
__device__ int   g_is64;
__device__ int   g_deg[NMAX];
__device__ int   g_off[NMAX + 1];
__device__ int   g_cur[NMAX];
__device__ int   g_bsum[64];                  // per-block sums for scan
__device__ int   g_boff[64];                  // scanned block offsets
__device__ uint2 g_elist[EMAX];               // (src, edge_id) sorted by dst

// ---------------- zero counters + stats each replay ------------------------------
__global__ void zero_kernel(int n) {
    int i = blockIdx.x * blockDim.x + threadIdx.x;
    if (i < n) g_deg[i] = 0;
    if (blockIdx.x == 0) {
        for (int j = threadIdx.x; j < 768; j += blockDim.x) g_stat[j] = 0.0f;
    }
}

// ---------------- detect edge_index dtype (int64 vs silently-downcast int32) ----
__global__ void detect_kernel(const unsigned long long* __restrict__ p, int n_nodes) {
    if (threadIdx.x == 0) {
        int ok = 1;
        for (int i = 0; i < 64; i++)
            if (p[i] >= (unsigned long long)n_nodes) { ok = 0; break; }
        g_is64 = ok;
    }
}

__device__ __forceinline__ void load_edge(const void* eiv, int e, int E,
                                          int& src, int& dst) {
    if (g_is64) {
        const long long* pe = (const long long*)eiv;
        src = (int)pe[e]; dst = (int)pe[(size_t)E + e];
    } else {
        const int* pe = (const int*)eiv;
        src = pe[e]; dst = pe[(size_t)E + e];
    }
}

// ---------------- CSR build: histogram ------------------------------------------
__global__ void hist_kernel(const void* __restrict__ eiv, int E) {
    int e = blockIdx.x * blockDim.x + threadIdx.x;
    if (e >= E) return;
    int src, dst; load_edge(eiv, e, E, src, dst);
    atomicAdd(&g_deg[dst], 1);
}

// ---------------- scan phase 1: per-block warp-shuffle scan ----------------------
__global__ __launch_bounds__(SCAN_B) void scan1_kernel(int n) {
    __shared__ int wsum[32];
    int tid = threadIdx.x;
    int lane = tid & 31, wid = tid >> 5;
    int i = blockIdx.x * SCAN_B + tid;
    int v = (i < n) ? g_deg[i] : 0;
    int x = v;
#pragma unroll
    for (int off = 1; off < 32; off <<= 1) {
        int t = __shfl_up_sync(FULLM, x, off);
        if (lane >= off) x += t;
    }
    if (lane == 31) wsum[wid] = x;
    __syncthreads();
    if (wid == 0) {
        int s = wsum[lane];
#pragma unroll
        for (int off = 1; off < 32; off <<= 1) {
            int t = __shfl_up_sync(FULLM, s, off);
            if (lane >= off) s += t;
        }
        wsum[lane] = s;
        if (lane == 31) g_bsum[blockIdx.x] = s;
    }
    __syncthreads();
    int base = (wid > 0) ? wsum[wid - 1] : 0;
    if (i < n) g_off[i] = base + x - v;  // exclusive within block
}

// ---------------- scan phase 2: scan the block sums (1 warp) ---------------------
__global__ void scan2_kernel(int nblocks, int n) {
    int lane = threadIdx.x;
    int v = (lane < nblocks) ? g_bsum[lane] : 0;
    int x = v;
#pragma unroll
    for (int off = 1; off < 32; off <<= 1) {
        int t = __shfl_up_sync(FULLM, x, off);
        if (lane >= off) x += t;
    }
    // supports up to 64 blocks via second pass
    if (nblocks > 32) {
        __shared__ int c32;
        if (lane == 31) c32 = x;
        __syncwarp();
        int v2 = (lane + 32 < nblocks) ? g_bsum[lane + 32] : 0;
        int x2 = v2;
#pragma unroll
        for (int off = 1; off < 32; off <<= 1) {
            int t = __shfl_up_sync(FULLM, x2, off);
            if (lane >= off) x2 += t;
        }
        if (lane < nblocks) g_boff[lane] = x - v;
        if (lane + 32 < nblocks) g_boff[lane + 32] = c32 + x2 - v2;
        if (lane == 31) g_off[n] = c32 + __shfl_sync(FULLM, x2, 31);
    } else {
        if (lane < nblocks) g_boff[lane] = x - v;
        if (lane == 31) g_off[n] = x;
    }
}

// ---------------- scan phase 3: add block offsets, init cursors ------------------
__global__ __launch_bounds__(SCAN_B) void scan3_kernel(int n) {
    int i = blockIdx.x * SCAN_B + threadIdx.x;
    if (i < n) {
        int o = g_off[i] + g_boff[blockIdx.x];
        g_off[i] = o;
        g_cur[i] = o;
    }
}

// ---------------- CSR build: scatter (src, e) by dst ------------------------------
__global__ void scatter_kernel(const void* __restrict__ eiv, int E) {
    int e = blockIdx.x * blockDim.x + threadIdx.x;
    if (e >= E) return;
    int src, dst; load_edge(eiv, e, E, src, dst);
    int pos = atomicAdd(&g_cur[dst], 1);
    g_elist[pos] = make_uint2((unsigned)src, (unsigned)e);
}

// ---------------- aggregation: 1 warp = 1 dst node --------------------------------
__global__ __launch_bounds__(256) void aggr_kernel(
    const float4* __restrict__ x4, const float* __restrict__ ea,
    const float4* __restrict__ We4, const float4* __restrict__ be4, int n)
{
    __shared__ float4 sW[512];  // W_edge: 16 x 128 floats
    __shared__ float4 sB[32];   // b_edge
    int t = threadIdx.x;
    sW[t]       = We4[t];
    sW[t + 256] = We4[t + 256];
    if (t < 32) sB[t] = be4[t];
    __syncthreads();

    int lane = t & 31;
    int dst = blockIdx.x * 8 + (t >> 5);
    if (dst >= n) return;

    int beg = g_off[dst], end = g_off[dst + 1];
    float4 acc = make_float4(0.f, 0.f, 0.f, 0.f);

    for (int b = beg; b < end; b += 32) {
        int cnt = min(32, end - b);
        uint2 se = (lane < cnt) ? g_elist[b + lane] : make_uint2(0u, 0u);
        float av[16];
        if (lane < cnt) {
            const float4* pa = (const float4*)(ea + (size_t)se.y * 16);
            float4 a0 = pa[0], a1 = pa[1], a2 = pa[2], a3 = pa[3];
            av[0]=a0.x; av[1]=a0.y; av[2]=a0.z; av[3]=a0.w;
            av[4]=a1.x; av[5]=a1.y; av[6]=a1.z; av[7]=a1.w;
            av[8]=a2.x; av[9]=a2.y; av[10]=a2.z; av[11]=a2.w;
            av[12]=a3.x; av[13]=a3.y; av[14]=a3.z; av[15]=a3.w;
        } else {
#pragma unroll
            for (int k = 0; k < 16; k++) av[k] = 0.f;
        }
        for (int j = 0; j < cnt; j++) {
            int srcj = __shfl_sync(FULLM, (int)se.x, j);
            float4 m = sB[lane];
#pragma unroll
            for (int k = 0; k < 16; k++) {
                float v = __shfl_sync(FULLM, av[k], j);
                float4 w = sW[k * 32 + lane];
                m.x = fmaf(v, w.x, m.x);
                m.y = fmaf(v, w.y, m.y);
                m.z = fmaf(v, w.z, m.z);
                m.w = fmaf(v, w.w, m.w);
            }
            float4 xv = x4[(size_t)srcj * 32 + lane];
            acc.x += fmaxf(m.x + xv.x, 0.0f);
            acc.y += fmaxf(m.y + xv.y, 0.0f);
            acc.z += fmaxf(m.z + xv.z, 0.0f);
            acc.w += fmaxf(m.w + xv.w, 0.0f);
        }
    }
    *(float4*)(g_aggr + (size_t)dst * EMB + lane * 4) = acc;
}

// ---------------- GEMM1: h1 = ((1+eps)*x + aggr) @ W1 + b1  (M x 256, K=128) ----
__global__ __launch_bounds__(256, 2) void gemm1_kernel(
    const float* __restrict__ X, const float* __restrict__ W,
    const float* __restrict__ bias, const float* __restrict__ epsp, int M)
{
    __shared__ float As[16][132];
    __shared__ float Bs[16][132];
    const float eps1 = 1.0f + *epsp;
    int t = threadIdx.x;
    int tx = t & 15, ty = t >> 4;
    int row0 = blockIdx.x * 128;
    int col0 = blockIdx.y * 128;
    float acc[8][8] = {};

    for (int kt = 0; kt < 128; kt += 16) {
#pragma unroll
        for (int l = 0; l < 2; l++) {
            int f = t + l * 256;
            int r = f >> 2, kq = (f & 3) * 4;
            int m = row0 + r;
            float4 v = make_float4(0.f, 0.f, 0.f, 0.f);
            if (m < M) {
                float4 xv = *(const float4*)(X + (size_t)m * 128 + kt + kq);
                float4 av = *(const float4*)(g_aggr + (size_t)m * 128 + kt + kq);
                v.x = fmaf(eps1, xv.x, av.x);
                v.y = fmaf(eps1, xv.y, av.y);
                v.z = fmaf(eps1, xv.z, av.z);
                v.w = fmaf(eps1, xv.w, av.w);
            }
            As[kq + 0][r] = v.x; As[kq + 1][r] = v.y;
            As[kq + 2][r] = v.z; As[kq + 3][r] = v.w;
        }
#pragma unroll
        for (int l = 0; l < 2; l++) {
            int f = t + l * 256;
            int kr = f >> 5, nc = (f & 31) * 4;
            *(float4*)&Bs[kr][nc] =
                *(const float4*)(W + (size_t)(kt + kr) * 256 + col0 + nc);
        }
        __syncthreads();
#pragma unroll
        for (int kk = 0; kk < 16; kk++) {
            float a0[8], b0[8];
            *(float4*)(a0)     = *(const float4*)&As[kk][ty * 4];
            *(float4*)(a0 + 4) = *(const float4*)&As[kk][64 + ty * 4];
            *(float4*)(b0)     = *(const float4*)&Bs[kk][tx * 4];
            *(float4*)(b0 + 4) = *(const float4*)&Bs[kk][64 + tx * 4];
#pragma unroll
            for (int i = 0; i < 8; i++)
#pragma unroll
                for (int j = 0; j < 8; j++)
                    acc[i][j] = fmaf(a0[i], b0[j], acc[i][j]);
        }
        __syncthreads();
    }
#pragma unroll
    for (int i = 0; i < 8; i++) {
        int m = row0 + ((i < 4) ? (ty * 4 + i) : (64 + ty * 4 + i - 4));
        if (m >= M) continue;
#pragma unroll
        for (int h = 0; h < 2; h++) {
            int c = col0 + h * 64 + tx * 4;
            float4 bb = *(const float4*)(bias + c);
            float4 o;
            o.x = acc[i][h * 4 + 0] + bb.x;
            o.y = acc[i][h * 4 + 1] + bb.y;
            o.z = acc[i][h * 4 + 2] + bb.z;
            o.w = acc[i][h * 4 + 3] + bb.w;
            *(float4*)(g_h1 + (size_t)m * 256 + c) = o;
        }
    }
}

// ---------------- column stats for h1 (256 cols) ---------------------------------
__global__ void stats1_kernel(int M) {
    int col = threadIdx.x;  // 256
    int r0 = blockIdx.x * 256;
    int r1 = min(r0 + 256, M);
    float s = 0.f, q = 0.f;
    for (int r = r0; r < r1; r++) {
        float v = g_h1[(size_t)r * 256 + col];
        s += v; q = fmaf(v, v, q);
    }
    atomicAdd(&g_stat[col], s);
    atomicAdd(&g_stat[256 + col], q);
}

// ---------------- column stats for h2 (128 cols, reads d_out) --------------------
__global__ void stats2_kernel(const float* __restrict__ H, int M) {
    int col = threadIdx.x;  // 128
    int r0 = blockIdx.x * 256;
    int r1 = min(r0 + 256, M);
    float s = 0.f, q = 0.f;
    for (int r = r0; r < r1; r++) {
        float v = H[(size_t)r * 128 + col];
        s += v; q = fmaf(v, v, q);
    }
    atomicAdd(&g_stat[512 + col], s);
    atomicAdd(&g_stat[640 + col], q);
}

// ---------------- finalize BN stats into fused scale/shift -----------------------
__global__ void finalize_kernel(const float* __restrict__ gam,
                                const float* __restrict__ bet,
                                int which, float invM)
{
    int c = threadIdx.x;
    float mu, msq;
    if (which == 0) { mu = g_stat[c] * invM;       msq = g_stat[256 + c] * invM; }
    else            { mu = g_stat[512 + c] * invM; msq = g_stat[640 + c] * invM; }
    float var = msq - mu * mu;
    float sc = gam[c] * rsqrtf(var + 1e-5f);
    float sh = bet[c] - mu * sc;
    if (which == 0) { g_scale1[c] = sc; g_shift1[c] = sh; }
    else            { g_scale2[c] = sc; g_shift2[c] = sh; }
}

// ---------------- GEMM2: out = relu(BN1(h1)) @ W2 + b2  (M x 128, K=256) ---------
__global__ __launch_bounds__(256, 2) void gemm2_kernel(
    const float* __restrict__ W, const float* __restrict__ bias,
    float* __restrict__ out, int M)
{
    __shared__ float As[16][132];
    __shared__ float Bs[16][132];
    int t = threadIdx.x;
    int tx = t & 15, ty = t >> 4;
    int row0 = blockIdx.x * 128;
    float acc[8][8] = {};

    for (int kt = 0; kt < 256; kt += 16) {
#pragma unroll
        for (int l = 0; l < 2; l++) {
            int f = t + l * 256;
            int r = f >> 2, kq = (f & 3) * 4;
            int m = row0 + r;
            float4 v = make_float4(0.f, 0.f, 0.f, 0.f);
            if (m < M) {
                float4 hv = *(const float4*)(g_h1 + (size_t)m * 256 + kt + kq);
                float4 sc = *(const float4*)(g_scale1 + kt + kq);
                float4 sh = *(const float4*)(g_shift1 + kt + kq);
                v.x = fmaxf(fmaf(hv.x, sc.x, sh.x), 0.0f);
                v.y = fmaxf(fmaf(hv.y, sc.y, sh.y), 0.0f);
                v.z = fmaxf(fmaf(hv.z, sc.z, sh.z), 0.0f);
                v.w = fmaxf(fmaf(hv.w, sc.w, sh.w), 0.0f);
            }
            As[kq + 0][r] = v.x; As[kq + 1][r] = v.y;
            As[kq + 2][r] = v.z; As[kq + 3][r] = v.w;
        }
#pragma unroll
        for (int l = 0; l < 2; l++) {
            int f = t + l * 256;
            int kr = f >> 5, nc = (f & 31) * 4;
            *(float4*)&Bs[kr][nc] =
                *(const float4*)(W + (size_t)(kt + kr) * 128 + nc);
        }
        __syncthreads();
#pragma unroll
        for (int kk = 0; kk < 16; kk++) {
            float a0[8], b0[8];
            *(float4*)(a0)     = *(const float4*)&As[kk][ty * 4];
            *(float4*)(a0 + 4) = *(const float4*)&As[kk][64 + ty * 4];
            *(float4*)(b0)     = *(const float4*)&Bs[kk][tx * 4];
            *(float4*)(b0 + 4) = *(const float4*)&Bs[kk][64 + tx * 4];
#pragma unroll
            for (int i = 0; i < 8; i++)
#pragma unroll
                for (int j = 0; j < 8; j++)
                    acc[i][j] = fmaf(a0[i], b0[j], acc[i][j]);
        }
        __syncthreads();
    }
#pragma unroll
    for (int i = 0; i < 8; i++) {
        int m = row0 + ((i < 4) ? (ty * 4 + i) : (64 + ty * 4 + i - 4));
        if (m >= M) continue;
#pragma unroll
        for (int h = 0; h < 2; h++) {
            int c = h * 64 + tx * 4;
            float4 bb = *(const float4*)(bias + c);
            float4 o;
            o.x = acc[i][h * 4 + 0] + bb.x;
            o.y = acc[i][h * 4 + 1] + bb.y;
            o.z = acc[i][h * 4 + 2] + bb.z;
            o.w = acc[i][h * 4 + 3] + bb.w;
            *(float4*)(out + (size_t)m * 128 + c) = o;
        }
    }
}

// ---------------- Threefry-2x32, key = (0, 42) -----------------------------------
__device__ __forceinline__ uint2 threefry2x32_042(uint32_t x0, uint32_t x1)
{
    const uint32_t k0 = 0u, k1 = 42u;
    const uint32_t k2 = k0 ^ k1 ^ 0x1BD11BDAu;
    x0 += k0; x1 += k1;
#define TF_R(r) { x0 += x1; x1 = __funnelshift_l(x1, x1, r); x1 ^= x0; }
    TF_R(13) TF_R(15) TF_R(26) TF_R(6)
    x0 += k1; x1 += k2 + 1u;
    TF_R(17) TF_R(29) TF_R(16) TF_R(24)
    x0 += k2; x1 += k0 + 2u;
    TF_R(13) TF_R(15) TF_R(26) TF_R(6)
    x0 += k0; x1 += k1 + 3u;
    TF_R(17) TF_R(29) TF_R(16) TF_R(24)
    x0 += k1; x1 += k2 + 4u;
    TF_R(13) TF_R(15) TF_R(26) TF_R(6)
    x0 += k2; x1 += k0 + 5u;
#undef TF_R
    return make_uint2(x0, x1);
}

// ---------------- outer BN + dropout (JAX partitionable threefry) ----------------
__global__ void bn_dropout_kernel(float* __restrict__ out, int total)
{
    int t = blockIdx.x * blockDim.x + threadIdx.x;
    int i0 = t * 4;
    if (i0 >= total) return;
    float4 v = *(float4*)(out + i0);
    int c = i0 & 127;
    float4 sc = *(const float4*)(g_scale2 + c);
    float4 sh = *(const float4*)(g_shift2 + c);
    float vals[4] = { fmaf(v.x, sc.x, sh.x), fmaf(v.y, sc.y, sh.y),
                      fmaf(v.z, sc.z, sh.z), fmaf(v.w, sc.w, sh.w) };
    float res[4];
#pragma unroll
    for (int j = 0; j < 4; j++) {
        uint2 o = threefry2x32_042(0u, (uint32_t)(i0 + j));
        uint32_t bits = o.x ^ o.y;
        float u = __uint_as_float((bits >> 9) | 0x3f800000u) - 1.0f;
        res[j] = (u < 0.8f) ? vals[j] * 1.25f : 0.0f;
    }
    *(float4*)(out + i0) = make_float4(res[0], res[1], res[2], res[3]);
}

// ---------------- launch ----------------------------------------------------------
extern "C" void kernel_launch(void* const* d_in, const int* in_sizes, int n_in,
                              void* d_out, int out_size)
{
    const float* x      = (const float*)d_in[0];
    const void*  ei     = d_in[1];
    const float* ea     = (const float*)d_in[2];
    const float* W_edge = (const float*)d_in[3];
    const float* b_edge = (const float*)d_in[4];
    const float* epsp   = (const float*)d_in[5];
    const float* W1     = (const float*)d_in[6];
    const float* b1     = (const float*)d_in[7];
    const float* g1     = (const float*)d_in[8];
    const float* beta1  = (const float*)d_in[9];
    const float* W2     = (const float*)d_in[10];
    const float* b2     = (const float*)d_in[11];
    const float* g_o    = (const float*)d_in[12];
    const float* beta_o = (const float*)d_in[13];
    float* out = (float*)d_out;

    int M = in_sizes[0] / EMB;     // 50000
    int E = in_sizes[1] / 2;       // 800000
    float invM = 1.0f / (float)M;
    int nScanBlocks = (M + SCAN_B - 1) / SCAN_B;   // 49

    zero_kernel<<<(M + 255) / 256, 256>>>(M);
    detect_kernel<<<1, 1>>>((const unsigned long long*)ei, M);
    hist_kernel<<<(E + 255) / 256, 256>>>(ei, E);
    scan1_kernel<<<nScanBlocks, SCAN_B>>>(M);
    scan2_kernel<<<1, 32>>>(nScanBlocks, M);
    scan3_kernel<<<nScanBlocks, SCAN_B>>>(M);
    scatter_kernel<<<(E + 255) / 256, 256>>>(ei, E);
    aggr_kernel<<<(M + 7) / 8, 256>>>((const float4*)x, ea,
                                      (const float4*)W_edge, (const float4*)b_edge, M);
    int gM = (M + 127) / 128;
    gemm1_kernel<<<dim3(gM, 2), 256>>>(x, W1, b1, epsp, M);
    stats1_kernel<<<(M + 255) / 256, 256>>>(M);
    finalize_kernel<<<1, 256>>>(g1, beta1, 0, invM);
    gemm2_kernel<<<dim3(gM, 1), 256>>>(W2, b2, out, M);
    stats2_kernel<<<(M + 255) / 256, 128>>>(out, M);
    finalize_kernel<<<1, 128>>>(g_o, beta_o, 1, invM);
    bn_dropout_kernel<<<(out_size / 4 + 255) / 256, 256>>>(out, out_size);
}

// round 6
// speedup vs baseline: 1.3153x; 1.1835x over previous
#include <cuda_runtime.h>
#include <cstdint>

#define EMB 128
#define NMAX 50000
#define EMAX 800000
#define SCAN_B 1024
#define FULLM 0xffffffffu

// ---------------- scratch (static device globals; no allocation) ----------------
__device__ float g_aggr[NMAX * EMB];          // 25.6 MB
__device__ float g_h1[NMAX * 2 * EMB];        // 51.2 MB
__device__ float g_stat[768];                 // sum1[256] sq1[256] sum2[128] sq2[128]
__device__ float g_scale1[2 * EMB], g_shift1[2 * EMB];
__device__ float g_scale2[EMB],     g_shift2[EMB];
__device__ int   g_is64;
__device__ int   g_deg[NMAX];
__device__ int   g_off[NMAX + 1];
__device__ int   g_cur[NMAX];
__device__ int   g_bsum[64];
__device__ int   g_boff[64];
__device__ uint2 g_elist[EMAX];               // (src, edge_id) sorted by dst

// ---------------- zero counters + stats each replay ------------------------------
__global__ void zero_kernel(int n) {
    int i = blockIdx.x * blockDim.x + threadIdx.x;
    if (i < n) g_deg[i] = 0;
    if (blockIdx.x == 0) {
        for (int j = threadIdx.x; j < 768; j += blockDim.x) g_stat[j] = 0.0f;
    }
}

// ---------------- detect edge_index dtype ----------------------------------------
__global__ void detect_kernel(const unsigned long long* __restrict__ p, int n_nodes) {
    if (threadIdx.x == 0) {
        int ok = 1;
        for (int i = 0; i < 64; i++)
            if (p[i] >= (unsigned long long)n_nodes) { ok = 0; break; }
        g_is64 = ok;
    }
}

__device__ __forceinline__ void load_edge(const void* eiv, int e, int E,
                                          int& src, int& dst) {
    if (g_is64) {
        const long long* pe = (const long long*)eiv;
        src = (int)pe[e]; dst = (int)pe[(size_t)E + e];
    } else {
        const int* pe = (const int*)eiv;
        src = pe[e]; dst = pe[(size_t)E + e];
    }
}

// ---------------- CSR build: histogram -------------------------------------------
__global__ void hist_kernel(const void* __restrict__ eiv, int E) {
    int e = blockIdx.x * blockDim.x + threadIdx.x;
    if (e >= E) return;
    int src, dst; load_edge(eiv, e, E, src, dst);
    atomicAdd(&g_deg[dst], 1);
}

// ---------------- scan phase 1 ----------------------------------------------------
__global__ __launch_bounds__(SCAN_B) void scan1_kernel(int n) {
    __shared__ int wsum[32];
    int tid = threadIdx.x;
    int lane = tid & 31, wid = tid >> 5;
    int i = blockIdx.x * SCAN_B + tid;
    int v = (i < n) ? g_deg[i] : 0;
    int x = v;
#pragma unroll
    for (int off = 1; off < 32; off <<= 1) {
        int t = __shfl_up_sync(FULLM, x, off);
        if (lane >= off) x += t;
    }
    if (lane == 31) wsum[wid] = x;
    __syncthreads();
    if (wid == 0) {
        int s = wsum[lane];
#pragma unroll
        for (int off = 1; off < 32; off <<= 1) {
            int t = __shfl_up_sync(FULLM, s, off);
            if (lane >= off) s += t;
        }
        wsum[lane] = s;
        if (lane == 31) g_bsum[blockIdx.x] = s;
    }
    __syncthreads();
    int base = (wid > 0) ? wsum[wid - 1] : 0;
    if (i < n) g_off[i] = base + x - v;
}

// ---------------- scan phase 2 ----------------------------------------------------
__global__ void scan2_kernel(int nblocks, int n) {
    int lane = threadIdx.x;
    int v = (lane < nblocks) ? g_bsum[lane] : 0;
    int x = v;
#pragma unroll
    for (int off = 1; off < 32; off <<= 1) {
        int t = __shfl_up_sync(FULLM, x, off);
        if (lane >= off) x += t;
    }
    if (nblocks > 32) {
        __shared__ int c32;
        if (lane == 31) c32 = x;
        __syncwarp();
        int v2 = (lane + 32 < nblocks) ? g_bsum[lane + 32] : 0;
        int x2 = v2;
#pragma unroll
        for (int off = 1; off < 32; off <<= 1) {
            int t = __shfl_up_sync(FULLM, x2, off);
            if (lane >= off) x2 += t;
        }
        if (lane < nblocks) g_boff[lane] = x - v;
        if (lane + 32 < nblocks) g_boff[lane + 32] = c32 + x2 - v2;
        if (lane == 31) g_off[n] = c32 + __shfl_sync(FULLM, x2, 31);
    } else {
        if (lane < nblocks) g_boff[lane] = x - v;
        if (lane == 31) g_off[n] = x;
    }
}

// ---------------- scan phase 3 ----------------------------------------------------
__global__ __launch_bounds__(SCAN_B) void scan3_kernel(int n) {
    int i = blockIdx.x * SCAN_B + threadIdx.x;
    if (i < n) {
        int o = g_off[i] + g_boff[blockIdx.x];
        g_off[i] = o;
        g_cur[i] = o;
    }
}

// ---------------- CSR build: scatter ----------------------------------------------
__global__ void scatter_kernel(const void* __restrict__ eiv, int E) {
    int e = blockIdx.x * blockDim.x + threadIdx.x;
    if (e >= E) return;
    int src, dst; load_edge(eiv, e, E, src, dst);
    int pos = atomicAdd(&g_cur[dst], 1);
    g_elist[pos] = make_uint2((unsigned)src, (unsigned)e);
}

// ---------------- aggregation: 1 warp = 1 dst node, 2-edge unroll -----------------
__global__ __launch_bounds__(256) void aggr_kernel(
    const float4* __restrict__ x4, const float* __restrict__ ea,
    const float4* __restrict__ We4, const float4* __restrict__ be4, int n)
{
    __shared__ float4 sW[512];
    __shared__ float4 sB[32];
    int t = threadIdx.x;
    sW[t]       = We4[t];
    sW[t + 256] = We4[t + 256];
    if (t < 32) sB[t] = be4[t];
    __syncthreads();

    int lane = t & 31;
    int dst = blockIdx.x * 8 + (t >> 5);
    if (dst >= n) return;

    int beg = g_off[dst], end = g_off[dst + 1];
    float4 acc = make_float4(0.f, 0.f, 0.f, 0.f);

    for (int b = beg; b < end; b += 32) {
        int cnt = min(32, end - b);
        uint2 se = (lane < cnt) ? g_elist[b + lane] : make_uint2(0u, 0u);
        float av[16];
        if (lane < cnt) {
            const float4* pa = (const float4*)(ea + (size_t)se.y * 16);
            float4 a0 = pa[0], a1 = pa[1], a2 = pa[2], a3 = pa[3];
            av[0]=a0.x; av[1]=a0.y; av[2]=a0.z; av[3]=a0.w;
            av[4]=a1.x; av[5]=a1.y; av[6]=a1.z; av[7]=a1.w;
            av[8]=a2.x; av[9]=a2.y; av[10]=a2.z; av[11]=a2.w;
            av[12]=a3.x; av[13]=a3.y; av[14]=a3.z; av[15]=a3.w;
        } else {
#pragma unroll
            for (int k = 0; k < 16; k++) av[k] = 0.f;
        }
        for (int j = 0; j < cnt; j += 2) {
            int j1 = min(j + 1, cnt - 1);
            bool has1 = (j + 1 < cnt);
            int src0 = __shfl_sync(FULLM, (int)se.x, j);
            int src1 = __shfl_sync(FULLM, (int)se.x, j1);
            float4 xv0 = x4[(size_t)src0 * 32 + lane];
            float4 xv1 = x4[(size_t)src1 * 32 + lane];
            float4 m0 = sB[lane];
            float4 m1 = m0;
#pragma unroll
            for (int k = 0; k < 16; k++) {
                float v0 = __shfl_sync(FULLM, av[k], j);
                float v1 = __shfl_sync(FULLM, av[k], j1);
                float4 w = sW[k * 32 + lane];
                m0.x = fmaf(v0, w.x, m0.x);  m1.x = fmaf(v1, w.x, m1.x);
                m0.y = fmaf(v0, w.y, m0.y);  m1.y = fmaf(v1, w.y, m1.y);
                m0.z = fmaf(v0, w.z, m0.z);  m1.z = fmaf(v1, w.z, m1.z);
                m0.w = fmaf(v0, w.w, m0.w);  m1.w = fmaf(v1, w.w, m1.w);
            }
            acc.x += fmaxf(m0.x + xv0.x, 0.0f);
            acc.y += fmaxf(m0.y + xv0.y, 0.0f);
            acc.z += fmaxf(m0.z + xv0.z, 0.0f);
            acc.w += fmaxf(m0.w + xv0.w, 0.0f);
            if (has1) {
                acc.x += fmaxf(m1.x + xv1.x, 0.0f);
                acc.y += fmaxf(m1.y + xv1.y, 0.0f);
                acc.z += fmaxf(m1.z + xv1.z, 0.0f);
                acc.w += fmaxf(m1.w + xv1.w, 0.0f);
            }
        }
    }
    *(float4*)(g_aggr + (size_t)dst * EMB + lane * 4) = acc;
}

// ---------------- GEMM1: h1 = ((1+eps)*x + aggr) @ W1 + b1, double-buffered -------
#define G1_LOAD(buf, kt) do {                                                       \
    _Pragma("unroll")                                                               \
    for (int l = 0; l < 2; l++) {                                                   \
        int f = t + l * 256;                                                        \
        int r = f >> 2, kq = (f & 3) * 4;                                           \
        int m = row0 + r;                                                           \
        float4 v = make_float4(0.f, 0.f, 0.f, 0.f);                                 \
        if (m < M) {                                                                \
            float4 xv = *(const float4*)(X + (size_t)m * 128 + (kt) + kq);          \
            float4 av = *(const float4*)(g_aggr + (size_t)m * 128 + (kt) + kq);     \
            v.x = fmaf(eps1, xv.x, av.x);                                           \
            v.y = fmaf(eps1, xv.y, av.y);                                           \
            v.z = fmaf(eps1, xv.z, av.z);                                           \
            v.w = fmaf(eps1, xv.w, av.w);                                           \
        }                                                                           \
        As[buf][kq + 0][r] = v.x; As[buf][kq + 1][r] = v.y;                         \
        As[buf][kq + 2][r] = v.z; As[buf][kq + 3][r] = v.w;                         \
    }                                                                               \
    _Pragma("unroll")                                                               \
    for (int l = 0; l < 2; l++) {                                                   \
        int f = t + l * 256;                                                        \
        int kr = f >> 5, nc = (f & 31) * 4;                                         \
        *(float4*)&Bs[buf][kr][nc] =                                                \
            *(const float4*)(W + (size_t)((kt) + kr) * 256 + col0 + nc);            \
    }                                                                               \
} while (0)

__global__ __launch_bounds__(256, 2) void gemm1_kernel(
    const float* __restrict__ X, const float* __restrict__ W,
    const float* __restrict__ bias, const float* __restrict__ epsp, int M)
{
    __shared__ float As[2][16][132];
    __shared__ float Bs[2][16][132];
    const float eps1 = 1.0f + *epsp;
    int t = threadIdx.x;
    int tx = t & 15, ty = t >> 4;
    int row0 = blockIdx.x * 128;
    int col0 = blockIdx.y * 128;
    float acc[8][8] = {};

    G1_LOAD(0, 0);
    __syncthreads();
    for (int kt = 0; kt < 128; kt += 16) {
        int cur = (kt >> 4) & 1;
        if (kt + 16 < 128) G1_LOAD(cur ^ 1, kt + 16);
#pragma unroll
        for (int kk = 0; kk < 16; kk++) {
            float a0[8], b0[8];
            *(float4*)(a0)     = *(const float4*)&As[cur][kk][ty * 4];
            *(float4*)(a0 + 4) = *(const float4*)&As[cur][kk][64 + ty * 4];
            *(float4*)(b0)     = *(const float4*)&Bs[cur][kk][tx * 4];
            *(float4*)(b0 + 4) = *(const float4*)&Bs[cur][kk][64 + tx * 4];
#pragma unroll
            for (int i = 0; i < 8; i++)
#pragma unroll
                for (int j = 0; j < 8; j++)
                    acc[i][j] = fmaf(a0[i], b0[j], acc[i][j]);
        }
        __syncthreads();
    }
#pragma unroll
    for (int i = 0; i < 8; i++) {
        int m = row0 + ((i < 4) ? (ty * 4 + i) : (64 + ty * 4 + i - 4));
        if (m >= M) continue;
#pragma unroll
        for (int h = 0; h < 2; h++) {
            int c = col0 + h * 64 + tx * 4;
            float4 bb = *(const float4*)(bias + c);
            float4 o;
            o.x = acc[i][h * 4 + 0] + bb.x;
            o.y = acc[i][h * 4 + 1] + bb.y;
            o.z = acc[i][h * 4 + 2] + bb.z;
            o.w = acc[i][h * 4 + 3] + bb.w;
            *(float4*)(g_h1 + (size_t)m * 256 + c) = o;
        }
    }
}

// ---------------- column stats for h1 (256 cols) ----------------------------------
__global__ void stats1_kernel(int M) {
    int col = threadIdx.x;  // 256
    int r0 = blockIdx.x * 256;
    int r1 = min(r0 + 256, M);
    float s = 0.f, q = 0.f;
    for (int r = r0; r < r1; r++) {
        float v = g_h1[(size_t)r * 256 + col];
        s += v; q = fmaf(v, v, q);
    }
    atomicAdd(&g_stat[col], s);
    atomicAdd(&g_stat[256 + col], q);
}

// ---------------- column stats for h2 (128 cols, reads d_out) ---------------------
__global__ void stats2_kernel(const float* __restrict__ H, int M) {
    int col = threadIdx.x;  // 128
    int r0 = blockIdx.x * 256;
    int r1 = min(r0 + 256, M);
    float s = 0.f, q = 0.f;
    for (int r = r0; r < r1; r++) {
        float v = H[(size_t)r * 128 + col];
        s += v; q = fmaf(v, v, q);
    }
    atomicAdd(&g_stat[512 + col], s);
    atomicAdd(&g_stat[640 + col], q);
}

// ---------------- finalize BN stats into fused scale/shift ------------------------
__global__ void finalize_kernel(const float* __restrict__ gam,
                                const float* __restrict__ bet,
                                int which, float invM)
{
    int c = threadIdx.x;
    float mu, msq;
    if (which == 0) { mu = g_stat[c] * invM;       msq = g_stat[256 + c] * invM; }
    else            { mu = g_stat[512 + c] * invM; msq = g_stat[640 + c] * invM; }
    float var = msq - mu * mu;
    float sc = gam[c] * rsqrtf(var + 1e-5f);
    float sh = bet[c] - mu * sc;
    if (which == 0) { g_scale1[c] = sc; g_shift1[c] = sh; }
    else            { g_scale2[c] = sc; g_shift2[c] = sh; }
}

// ---------------- GEMM2: out = relu(BN1(h1)) @ W2 + b2, double-buffered -----------
#define G2_LOAD(buf, kt) do {                                                       \
    _Pragma("unroll")                                                               \
    for (int l = 0; l < 2; l++) {                                                   \
        int f = t + l * 256;                                                        \
        int r = f >> 2, kq = (f & 3) * 4;                                           \
        int m = row0 + r;                                                           \
        float4 v = make_float4(0.f, 0.f, 0.f, 0.f);                                 \
        if (m < M) {                                                                \
            float4 hv = *(const float4*)(g_h1 + (size_t)m * 256 + (kt) + kq);       \
            float4 sc = *(const float4*)(g_scale1 + (kt) + kq);                     \
            float4 sh = *(const float4*)(g_shift1 + (kt) + kq);                     \
            v.x = fmaxf(fmaf(hv.x, sc.x, sh.x), 0.0f);                              \
            v.y = fmaxf(fmaf(hv.y, sc.y, sh.y), 0.0f);                              \
            v.z = fmaxf(fmaf(hv.z, sc.z, sh.z), 0.0f);                              \
            v.w = fmaxf(fmaf(hv.w, sc.w, sh.w), 0.0f);                              \
        }                                                                           \
        As[buf][kq + 0][r] = v.x; As[buf][kq + 1][r] = v.y;                         \
        As[buf][kq + 2][r] = v.z; As[buf][kq + 3][r] = v.w;                         \
    }                                                                               \
    _Pragma("unroll")                                                               \
    for (int l = 0; l < 2; l++) {                                                   \
        int f = t + l * 256;                                                        \
        int kr = f >> 5, nc = (f & 31) * 4;                                         \
        *(float4*)&Bs[buf][kr][nc] =                                                \
            *(const float4*)(W + (size_t)((kt) + kr) * 128 + nc);                   \
    }                                                                               \
} while (0)

__global__ __launch_bounds__(256, 2) void gemm2_kernel(
    const float* __restrict__ W, const float* __restrict__ bias,
    float* __restrict__ out, int M)
{
    __shared__ float As[2][16][132];
    __shared__ float Bs[2][16][132];
    int t = threadIdx.x;
    int tx = t & 15, ty = t >> 4;
    int row0 = blockIdx.x * 128;
    float acc[8][8] = {};

    G2_LOAD(0, 0);
    __syncthreads();
    for (int kt = 0; kt < 256; kt += 16) {
        int cur = (kt >> 4) & 1;
        if (kt + 16 < 256) G2_LOAD(cur ^ 1, kt + 16);
#pragma unroll
        for (int kk = 0; kk < 16; kk++) {
            float a0[8], b0[8];
            *(float4*)(a0)     = *(const float4*)&As[cur][kk][ty * 4];
            *(float4*)(a0 + 4) = *(const float4*)&As[cur][kk][64 + ty * 4];
            *(float4*)(b0)     = *(const float4*)&Bs[cur][kk][tx * 4];
            *(float4*)(b0 + 4) = *(const float4*)&Bs[cur][kk][64 + tx * 4];
#pragma unroll
            for (int i = 0; i < 8; i++)
#pragma unroll
                for (int j = 0; j < 8; j++)
                    acc[i][j] = fmaf(a0[i], b0[j], acc[i][j]);
        }
        __syncthreads();
    }
#pragma unroll
    for (int i = 0; i < 8; i++) {
        int m = row0 + ((i < 4) ? (ty * 4 + i) : (64 + ty * 4 + i - 4));
        if (m >= M) continue;
#pragma unroll
        for (int h = 0; h < 2; h++) {
            int c = h * 64 + tx * 4;
            float4 bb = *(const float4*)(bias + c);
            float4 o;
            o.x = acc[i][h * 4 + 0] + bb.x;
            o.y = acc[i][h * 4 + 1] + bb.y;
            o.z = acc[i][h * 4 + 2] + bb.z;
            o.w = acc[i][h * 4 + 3] + bb.w;
            *(float4*)(out + (size_t)m * 128 + c) = o;
        }
    }
}

// ---------------- Threefry-2x32, key = (0, 42) -------------------------------------
__device__ __forceinline__ uint2 threefry2x32_042(uint32_t x0, uint32_t x1)
{
    const uint32_t k0 = 0u, k1 = 42u;
    const uint32_t k2 = k0 ^ k1 ^ 0x1BD11BDAu;
    x0 += k0; x1 += k1;
#define TF_R(r) { x0 += x1; x1 = __funnelshift_l(x1, x1, r); x1 ^= x0; }
    TF_R(13) TF_R(15) TF_R(26) TF_R(6)
    x0 += k1; x1 += k2 + 1u;
    TF_R(17) TF_R(29) TF_R(16) TF_R(24)
    x0 += k2; x1 += k0 + 2u;
    TF_R(13) TF_R(15) TF_R(26) TF_R(6)
    x0 += k0; x1 += k1 + 3u;
    TF_R(17) TF_R(29) TF_R(16) TF_R(24)
    x0 += k1; x1 += k2 + 4u;
    TF_R(13) TF_R(15) TF_R(26) TF_R(6)
    x0 += k2; x1 += k0 + 5u;
#undef TF_R
    return make_uint2(x0, x1);
}

// ---------------- outer BN + dropout -----------------------------------------------
__global__ void bn_dropout_kernel(float* __restrict__ out, int total)
{
    int t = blockIdx.x * blockDim.x + threadIdx.x;
    int i0 = t * 4;
    if (i0 >= total) return;
    float4 v = *(float4*)(out + i0);
    int c = i0 & 127;
    float4 sc = *(const float4*)(g_scale2 + c);
    float4 sh = *(const float4*)(g_shift2 + c);
    float vals[4] = { fmaf(v.x, sc.x, sh.x), fmaf(v.y, sc.y, sh.y),
                      fmaf(v.z, sc.z, sh.z), fmaf(v.w, sc.w, sh.w) };
    float res[4];
#pragma unroll
    for (int j = 0; j < 4; j++) {
        uint2 o = threefry2x32_042(0u, (uint32_t)(i0 + j));
        uint32_t bits = o.x ^ o.y;
        float u = __uint_as_float((bits >> 9) | 0x3f800000u) - 1.0f;
        res[j] = (u < 0.8f) ? vals[j] * 1.25f : 0.0f;
    }
    *(float4*)(out + i0) = make_float4(res[0], res[1], res[2], res[3]);
}

// ---------------- launch ------------------------------------------------------------
extern "C" void kernel_launch(void* const* d_in, const int* in_sizes, int n_in,
                              void* d_out, int out_size)
{
    const float* x      = (const float*)d_in[0];
    const void*  ei     = d_in[1];
    const float* ea     = (const float*)d_in[2];
    const float* W_edge = (const float*)d_in[3];
    const float* b_edge = (const float*)d_in[4];
    const float* epsp   = (const float*)d_in[5];
    const float* W1     = (const float*)d_in[6];
    const float* b1     = (const float*)d_in[7];
    const float* g1     = (const float*)d_in[8];
    const float* beta1  = (const float*)d_in[9];
    const float* W2     = (const float*)d_in[10];
    const float* b2     = (const float*)d_in[11];
    const float* g_o    = (const float*)d_in[12];
    const float* beta_o = (const float*)d_in[13];
    float* out = (float*)d_out;

    int M = in_sizes[0] / EMB;     // 50000
    int E = in_sizes[1] / 2;       // 800000
    float invM = 1.0f / (float)M;
    int nScanBlocks = (M + SCAN_B - 1) / SCAN_B;

    zero_kernel<<<(M + 255) / 256, 256>>>(M);
    detect_kernel<<<1, 1>>>((const unsigned long long*)ei, M);
    hist_kernel<<<(E + 255) / 256, 256>>>(ei, E);
    scan1_kernel<<<nScanBlocks, SCAN_B>>>(M);
    scan2_kernel<<<1, 32>>>(nScanBlocks, M);
    scan3_kernel<<<nScanBlocks, SCAN_B>>>(M);
    scatter_kernel<<<(E + 255) / 256, 256>>>(ei, E);
    aggr_kernel<<<(M + 7) / 8, 256>>>((const float4*)x, ea,
                                      (const float4*)W_edge, (const float4*)b_edge, M);
    int gM = (M + 127) / 128;
    gemm1_kernel<<<dim3(gM, 2), 256>>>(x, W1, b1, epsp, M);
    stats1_kernel<<<(M + 255) / 256, 256>>>(M);
    finalize_kernel<<<1, 256>>>(g1, beta1, 0, invM);
    gemm2_kernel<<<gM, 256>>>(W2, b2, out, M);
    stats2_kernel<<<(M + 255) / 256, 128>>>(out, M);
    finalize_kernel<<<1, 128>>>(g_o, beta_o, 1, invM);
    bn_dropout_kernel<<<(out_size / 4 + 255) / 256, 256>>>(out, out_size);
}

// round 7
// speedup vs baseline: 1.5329x; 1.1654x over previous
#include <cuda_runtime.h>
#include <cstdint>

#define EMB 128
#define NMAX 50000
#define EMAX 800000
#define SCAN_B 1024
#define FULLM 0xffffffffu

typedef unsigned long long ull;

// ---------------- f32x2 packed helpers --------------------------------------------
#define FMA2(d, a, b, c) \
    asm("fma.rn.f32x2 %0, %1, %2, %3;" : "=l"(d) : "l"(a), "l"(b), "l"(c))
#define PACK2(d, x) \
    asm("mov.b64 %0, {%1, %1};" : "=l"(d) : "f"(x))
#define PACKAB(d, x, y) \
    asm("mov.b64 %0, {%1, %2};" : "=l"(d) : "f"(x), "f"(y))
#define UNPACK2(lo, hi, v) \
    asm("mov.b64 {%0, %1}, %2;" : "=f"(lo), "=f"(hi) : "l"(v))

// ---------------- scratch (static device globals; no allocation) ----------------
__device__ float g_aggr[NMAX * EMB];          // 25.6 MB
__device__ float g_h1[NMAX * 2 * EMB];        // 51.2 MB
__device__ float g_stat[768];                 // sum1[256] sq1[256] sum2[128] sq2[128]
__device__ float g_scale1[2 * EMB], g_shift1[2 * EMB];
__device__ float g_scale2[EMB],     g_shift2[EMB];
__device__ int   g_is64;
__device__ int   g_deg[NMAX];
__device__ int   g_off[NMAX + 1];
__device__ int   g_cur[NMAX];
__device__ int   g_bsum[64];
__device__ int   g_boff[64];
__device__ uint2 g_elist[EMAX];               // (src, edge_id) sorted by dst

// ---------------- zero counters + stats each replay ------------------------------
__global__ void zero_kernel(int n) {
    int i = blockIdx.x * blockDim.x + threadIdx.x;
    if (i < n) g_deg[i] = 0;
    if (blockIdx.x == 0) {
        for (int j = threadIdx.x; j < 768; j += blockDim.x) g_stat[j] = 0.0f;
    }
}

// ---------------- detect edge_index dtype ----------------------------------------
__global__ void detect_kernel(const unsigned long long* __restrict__ p, int n_nodes) {
    if (threadIdx.x == 0) {
        int ok = 1;
        for (int i = 0; i < 64; i++)
            if (p[i] >= (unsigned long long)n_nodes) { ok = 0; break; }
        g_is64 = ok;
    }
}

__device__ __forceinline__ void load_edge(const void* eiv, int e, int E,
                                          int& src, int& dst) {
    if (g_is64) {
        const long long* pe = (const long long*)eiv;
        src = (int)pe[e]; dst = (int)pe[(size_t)E + e];
    } else {
        const int* pe = (const int*)eiv;
        src = pe[e]; dst = pe[(size_t)E + e];
    }
}

// ---------------- CSR build: histogram -------------------------------------------
__global__ void hist_kernel(const void* __restrict__ eiv, int E) {
    int e = blockIdx.x * blockDim.x + threadIdx.x;
    if (e >= E) return;
    int src, dst; load_edge(eiv, e, E, src, dst);
    atomicAdd(&g_deg[dst], 1);
}

// ---------------- scan phase 1 ----------------------------------------------------
__global__ __launch_bounds__(SCAN_B) void scan1_kernel(int n) {
    __shared__ int wsum[32];
    int tid = threadIdx.x;
    int lane = tid & 31, wid = tid >> 5;
    int i = blockIdx.x * SCAN_B + tid;
    int v = (i < n) ? g_deg[i] : 0;
    int x = v;
#pragma unroll
    for (int off = 1; off < 32; off <<= 1) {
        int t = __shfl_up_sync(FULLM, x, off);
        if (lane >= off) x += t;
    }
    if (lane == 31) wsum[wid] = x;
    __syncthreads();
    if (wid == 0) {
        int s = wsum[lane];
#pragma unroll
        for (int off = 1; off < 32; off <<= 1) {
            int t = __shfl_up_sync(FULLM, s, off);
            if (lane >= off) s += t;
        }
        wsum[lane] = s;
        if (lane == 31) g_bsum[blockIdx.x] = s;
    }
    __syncthreads();
    int base = (wid > 0) ? wsum[wid - 1] : 0;
    if (i < n) g_off[i] = base + x - v;
}

// ---------------- scan phase 2 ----------------------------------------------------
__global__ void scan2_kernel(int nblocks, int n) {
    int lane = threadIdx.x;
    int v = (lane < nblocks) ? g_bsum[lane] : 0;
    int x = v;
#pragma unroll
    for (int off = 1; off < 32; off <<= 1) {
        int t = __shfl_up_sync(FULLM, x, off);
        if (lane >= off) x += t;
    }
    if (nblocks > 32) {
        __shared__ int c32;
        if (lane == 31) c32 = x;
        __syncwarp();
        int v2 = (lane + 32 < nblocks) ? g_bsum[lane + 32] : 0;
        int x2 = v2;
#pragma unroll
        for (int off = 1; off < 32; off <<= 1) {
            int t = __shfl_up_sync(FULLM, x2, off);
            if (lane >= off) x2 += t;
        }
        if (lane < nblocks) g_boff[lane] = x - v;
        if (lane + 32 < nblocks) g_boff[lane + 32] = c32 + x2 - v2;
        if (lane == 31) g_off[n] = c32 + __shfl_sync(FULLM, x2, 31);
    } else {
        if (lane < nblocks) g_boff[lane] = x - v;
        if (lane == 31) g_off[n] = x;
    }
}

// ---------------- scan phase 3 ----------------------------------------------------
__global__ __launch_bounds__(SCAN_B) void scan3_kernel(int n) {
    int i = blockIdx.x * SCAN_B + threadIdx.x;
    if (i < n) {
        int o = g_off[i] + g_boff[blockIdx.x];
        g_off[i] = o;
        g_cur[i] = o;
    }
}

// ---------------- CSR build: scatter ----------------------------------------------
__global__ void scatter_kernel(const void* __restrict__ eiv, int E) {
    int e = blockIdx.x * blockDim.x + threadIdx.x;
    if (e >= E) return;
    int src, dst; load_edge(eiv, e, E, src, dst);
    int pos = atomicAdd(&g_cur[dst], 1);
    g_elist[pos] = make_uint2((unsigned)src, (unsigned)e);
}

// ---------------- aggregation: 1 warp = 1 dst, W in regs, FFMA2 -------------------
__global__ __launch_bounds__(256) void aggr_kernel(
    const float4* __restrict__ x4, const float* __restrict__ ea,
    const float4* __restrict__ We4, const float4* __restrict__ be4, int n)
{
    // per-warp staging of duplicated edge_attr pairs: [warp][edge j][k] = {v, v}
    __shared__ float2 s_av[8][32][18];   // stride 18 float2 = 144B (16B-aligned, conflict-light)
    int t = threadIdx.x, lane = t & 31, warp = t >> 5;

    // this lane's W_edge column slice (cols lane*4 .. lane*4+3) in registers
    ull w01[16], w23[16];
#pragma unroll
    for (int k = 0; k < 16; k++) {
        float4 w = We4[k * 32 + lane];
        PACKAB(w01[k], w.x, w.y);
        PACKAB(w23[k], w.z, w.w);
    }
    float4 bia = be4[lane];
    ull b01, b23;
    PACKAB(b01, bia.x, bia.y);
    PACKAB(b23, bia.z, bia.w);

    int dst = blockIdx.x * 8 + warp;
    if (dst >= n) return;

    int beg = g_off[dst], end = g_off[dst + 1];
    float4 acc = make_float4(0.f, 0.f, 0.f, 0.f);

    for (int b = beg; b < end; b += 32) {
        int cnt = min(32, end - b);
        uint2 se = (lane < cnt) ? g_elist[b + lane] : make_uint2(0u, 0u);
        if (lane < cnt) {
            const float4* pa = (const float4*)(ea + (size_t)se.y * 16);
            float4* dstp = (float4*)&s_av[warp][lane][0];
#pragma unroll
            for (int q = 0; q < 4; q++) {
                float4 a = pa[q];
                dstp[q * 2 + 0] = make_float4(a.x, a.x, a.y, a.y);
                dstp[q * 2 + 1] = make_float4(a.z, a.z, a.w, a.w);
            }
        }
        __syncwarp();
        for (int j = 0; j < cnt; j++) {
            int srcj = __shfl_sync(FULLM, (int)se.x, j);
            float4 xv = x4[(size_t)srcj * 32 + lane];
            ull m01 = b01, m23 = b23;
            const ull* avp = (const ull*)&s_av[warp][j][0];
#pragma unroll
            for (int k = 0; k < 16; k++) {
                ull vv = avp[k];              // LDS.64 broadcast (same addr all lanes)
                FMA2(m01, vv, w01[k], m01);
                FMA2(m23, vv, w23[k], m23);
            }
            float f0, f1, f2, f3;
            UNPACK2(f0, f1, m01);
            UNPACK2(f2, f3, m23);
            acc.x += fmaxf(f0 + xv.x, 0.0f);
            acc.y += fmaxf(f1 + xv.y, 0.0f);
            acc.z += fmaxf(f2 + xv.z, 0.0f);
            acc.w += fmaxf(f3 + xv.w, 0.0f);
        }
        __syncwarp();
    }
    *(float4*)(g_aggr + (size_t)dst * EMB + lane * 4) = acc;
}

// ---------------- GEMM1: h1 = ((1+eps)*x + aggr) @ W1 + b1, dbuf + FFMA2 ----------
#define G1_LOAD(buf, kt) do {                                                       \
    _Pragma("unroll")                                                               \
    for (int l = 0; l < 2; l++) {                                                   \
        int f = t + l * 256;                                                        \
        int r = f >> 2, kq = (f & 3) * 4;                                           \
        int m = row0 + r;                                                           \
        float4 v = make_float4(0.f, 0.f, 0.f, 0.f);                                 \
        if (m < M) {                                                                \
            float4 xv = *(const float4*)(X + (size_t)m * 128 + (kt) + kq);          \
            float4 av = *(const float4*)(g_aggr + (size_t)m * 128 + (kt) + kq);     \
            v.x = fmaf(eps1, xv.x, av.x);                                           \
            v.y = fmaf(eps1, xv.y, av.y);                                           \
            v.z = fmaf(eps1, xv.z, av.z);                                           \
            v.w = fmaf(eps1, xv.w, av.w);                                           \
        }                                                                           \
        As[buf][kq + 0][r] = v.x; As[buf][kq + 1][r] = v.y;                         \
        As[buf][kq + 2][r] = v.z; As[buf][kq + 3][r] = v.w;                         \
    }                                                                               \
    _Pragma("unroll")                                                               \
    for (int l = 0; l < 2; l++) {                                                   \
        int f = t + l * 256;                                                        \
        int kr = f >> 5, nc = (f & 31) * 4;                                         \
        *(float4*)&Bs[buf][kr][nc] =                                                \
            *(const float4*)(W + (size_t)((kt) + kr) * 256 + col0 + nc);            \
    }                                                                               \
} while (0)

#define GEMM_KK(cur) do {                                                           \
    _Pragma("unroll")                                                               \
    for (int kk = 0; kk < 16; kk++) {                                               \
        float a0[8], b0[8];                                                         \
        *(float4*)(a0)     = *(const float4*)&As[cur][kk][ty * 4];                  \
        *(float4*)(a0 + 4) = *(const float4*)&As[cur][kk][64 + ty * 4];             \
        *(float4*)(b0)     = *(const float4*)&Bs[cur][kk][tx * 4];                  \
        *(float4*)(b0 + 4) = *(const float4*)&Bs[cur][kk][64 + tx * 4];             \
        ull bp[4], ap[8];                                                           \
        _Pragma("unroll")                                                           \
        for (int j2 = 0; j2 < 4; j2++) PACKAB(bp[j2], b0[2 * j2], b0[2 * j2 + 1]);  \
        _Pragma("unroll")                                                           \
        for (int i = 0; i < 8; i++) PACK2(ap[i], a0[i]);                            \
        _Pragma("unroll")                                                           \
        for (int i = 0; i < 8; i++)                                                 \
            _Pragma("unroll")                                                       \
            for (int j2 = 0; j2 < 4; j2++)                                          \
                FMA2(acc2[i][j2], ap[i], bp[j2], acc2[i][j2]);                      \
    }                                                                               \
} while (0)

__global__ __launch_bounds__(256, 2) void gemm1_kernel(
    const float* __restrict__ X, const float* __restrict__ W,
    const float* __restrict__ bias, const float* __restrict__ epsp, int M)
{
    __shared__ float As[2][16][132];
    __shared__ float Bs[2][16][132];
    const float eps1 = 1.0f + *epsp;
    int t = threadIdx.x;
    int tx = t & 15, ty = t >> 4;
    int row0 = blockIdx.x * 128;
    int col0 = blockIdx.y * 128;
    ull acc2[8][4] = {};

    G1_LOAD(0, 0);
    __syncthreads();
    for (int kt = 0; kt < 128; kt += 16) {
        int cur = (kt >> 4) & 1;
        if (kt + 16 < 128) G1_LOAD(cur ^ 1, kt + 16);
        GEMM_KK(cur);
        __syncthreads();
    }
    float acc[8][8];
#pragma unroll
    for (int i = 0; i < 8; i++)
#pragma unroll
        for (int j2 = 0; j2 < 4; j2++)
            UNPACK2(acc[i][2 * j2], acc[i][2 * j2 + 1], acc2[i][j2]);
#pragma unroll
    for (int i = 0; i < 8; i++) {
        int m = row0 + ((i < 4) ? (ty * 4 + i) : (64 + ty * 4 + i - 4));
        if (m >= M) continue;
#pragma unroll
        for (int h = 0; h < 2; h++) {
            int c = col0 + h * 64 + tx * 4;
            float4 bb = *(const float4*)(bias + c);
            float4 o;
            o.x = acc[i][h * 4 + 0] + bb.x;
            o.y = acc[i][h * 4 + 1] + bb.y;
            o.z = acc[i][h * 4 + 2] + bb.z;
            o.w = acc[i][h * 4 + 3] + bb.w;
            *(float4*)(g_h1 + (size_t)m * 256 + c) = o;
        }
    }
}

// ---------------- column stats for h1 (256 cols) ----------------------------------
__global__ void stats1_kernel(int M) {
    int col = threadIdx.x;  // 256
    int r0 = blockIdx.x * 256;
    int r1 = min(r0 + 256, M);
    float s = 0.f, q = 0.f;
    for (int r = r0; r < r1; r++) {
        float v = g_h1[(size_t)r * 256 + col];
        s += v; q = fmaf(v, v, q);
    }
    atomicAdd(&g_stat[col], s);
    atomicAdd(&g_stat[256 + col], q);
}

// ---------------- column stats for h2 (128 cols, reads d_out) ---------------------
__global__ void stats2_kernel(const float* __restrict__ H, int M) {
    int col = threadIdx.x;  // 128
    int r0 = blockIdx.x * 256;
    int r1 = min(r0 + 256, M);
    float s = 0.f, q = 0.f;
    for (int r = r0; r < r1; r++) {
        float v = H[(size_t)r * 128 + col];
        s += v; q = fmaf(v, v, q);
    }
    atomicAdd(&g_stat[512 + col], s);
    atomicAdd(&g_stat[640 + col], q);
}

// ---------------- finalize BN stats into fused scale/shift ------------------------
__global__ void finalize_kernel(const float* __restrict__ gam,
                                const float* __restrict__ bet,
                                int which, float invM)
{
    int c = threadIdx.x;
    float mu, msq;
    if (which == 0) { mu = g_stat[c] * invM;       msq = g_stat[256 + c] * invM; }
    else            { mu = g_stat[512 + c] * invM; msq = g_stat[640 + c] * invM; }
    float var = msq - mu * mu;
    float sc = gam[c] * rsqrtf(var + 1e-5f);
    float sh = bet[c] - mu * sc;
    if (which == 0) { g_scale1[c] = sc; g_shift1[c] = sh; }
    else            { g_scale2[c] = sc; g_shift2[c] = sh; }
}

// ---------------- GEMM2: out = relu(BN1(h1)) @ W2 + b2, dbuf + FFMA2 --------------
#define G2_LOAD(buf, kt) do {                                                       \
    _Pragma("unroll")                                                               \
    for (int l = 0; l < 2; l++) {                                                   \
        int f = t + l * 256;                                                        \
        int r = f >> 2, kq = (f & 3) * 4;                                           \
        int m = row0 + r;                                                           \
        float4 v = make_float4(0.f, 0.f, 0.f, 0.f);                                 \
        if (m < M) {                                                                \
            float4 hv = *(const float4*)(g_h1 + (size_t)m * 256 + (kt) + kq);       \
            float4 sc = *(const float4*)(g_scale1 + (kt) + kq);                     \
            float4 sh = *(const float4*)(g_shift1 + (kt) + kq);                     \
            v.x = fmaxf(fmaf(hv.x, sc.x, sh.x), 0.0f);                              \
            v.y = fmaxf(fmaf(hv.y, sc.y, sh.y), 0.0f);                              \
            v.z = fmaxf(fmaf(hv.z, sc.z, sh.z), 0.0f);                              \
            v.w = fmaxf(fmaf(hv.w, sc.w, sh.w), 0.0f);                              \
        }                                                                           \
        As[buf][kq + 0][r] = v.x; As[buf][kq + 1][r] = v.y;                         \
        As[buf][kq + 2][r] = v.z; As[buf][kq + 3][r] = v.w;                         \
    }                                                                               \
    _Pragma("unroll")                                                               \
    for (int l = 0; l < 2; l++) {                                                   \
        int f = t + l * 256;                                                        \
        int kr = f >> 5, nc = (f & 31) * 4;                                         \
        *(float4*)&Bs[buf][kr][nc] =                                                \
            *(const float4*)(W + (size_t)((kt) + kr) * 128 + nc);                   \
    }                                                                               \
} while (0)

__global__ __launch_bounds__(256, 2) void gemm2_kernel(
    const float* __restrict__ W, const float* __restrict__ bias,
    float* __restrict__ out, int M)
{
    __shared__ float As[2][16][132];
    __shared__ float Bs[2][16][132];
    int t = threadIdx.x;
    int tx = t & 15, ty = t >> 4;
    int row0 = blockIdx.x * 128;
    ull acc2[8][4] = {};

    G2_LOAD(0, 0);
    __syncthreads();
    for (int kt = 0; kt < 256; kt += 16) {
        int cur = (kt >> 4) & 1;
        if (kt + 16 < 256) G2_LOAD(cur ^ 1, kt + 16);
        GEMM_KK(cur);
        __syncthreads();
    }
    float acc[8][8];
#pragma unroll
    for (int i = 0; i < 8; i++)
#pragma unroll
        for (int j2 = 0; j2 < 4; j2++)
            UNPACK2(acc[i][2 * j2], acc[i][2 * j2 + 1], acc2[i][j2]);
#pragma unroll
    for (int i = 0; i < 8; i++) {
        int m = row0 + ((i < 4) ? (ty * 4 + i) : (64 + ty * 4 + i - 4));
        if (m >= M) continue;
#pragma unroll
        for (int h = 0; h < 2; h++) {
            int c = h * 64 + tx * 4;
            float4 bb = *(const float4*)(bias + c);
            float4 o;
            o.x = acc[i][h * 4 + 0] + bb.x;
            o.y = acc[i][h * 4 + 1] + bb.y;
            o.z = acc[i][h * 4 + 2] + bb.z;
            o.w = acc[i][h * 4 + 3] + bb.w;
            *(float4*)(out + (size_t)m * 128 + c) = o;
        }
    }
}

// ---------------- Threefry-2x32, key = (0, 42) -------------------------------------
__device__ __forceinline__ uint2 threefry2x32_042(uint32_t x0, uint32_t x1)
{
    const uint32_t k0 = 0u, k1 = 42u;
    const uint32_t k2 = k0 ^ k1 ^ 0x1BD11BDAu;
    x0 += k0; x1 += k1;
#define TF_R(r) { x0 += x1; x1 = __funnelshift_l(x1, x1, r); x1 ^= x0; }
    TF_R(13) TF_R(15) TF_R(26) TF_R(6)
    x0 += k1; x1 += k2 + 1u;
    TF_R(17) TF_R(29) TF_R(16) TF_R(24)
    x0 += k2; x1 += k0 + 2u;
    TF_R(13) TF_R(15) TF_R(26) TF_R(6)
    x0 += k0; x1 += k1 + 3u;
    TF_R(17) TF_R(29) TF_R(16) TF_R(24)
    x0 += k1; x1 += k2 + 4u;
    TF_R(13) TF_R(15) TF_R(26) TF_R(6)
    x0 += k2; x1 += k0 + 5u;
#undef TF_R
    return make_uint2(x0, x1);
}

// ---------------- outer BN + dropout -----------------------------------------------
__global__ void bn_dropout_kernel(float* __restrict__ out, int total)
{
    int t = blockIdx.x * blockDim.x + threadIdx.x;
    int i0 = t * 4;
    if (i0 >= total) return;
    float4 v = *(float4*)(out + i0);
    int c = i0 & 127;
    float4 sc = *(const float4*)(g_scale2 + c);
    float4 sh = *(const float4*)(g_shift2 + c);
    float vals[4] = { fmaf(v.x, sc.x, sh.x), fmaf(v.y, sc.y, sh.y),
                      fmaf(v.z, sc.z, sh.z), fmaf(v.w, sc.w, sh.w) };
    float res[4];
#pragma unroll
    for (int j = 0; j < 4; j++) {
        uint2 o = threefry2x32_042(0u, (uint32_t)(i0 + j));
        uint32_t bits = o.x ^ o.y;
        float u = __uint_as_float((bits >> 9) | 0x3f800000u) - 1.0f;
        res[j] = (u < 0.8f) ? vals[j] * 1.25f : 0.0f;
    }
    *(float4*)(out + i0) = make_float4(res[0], res[1], res[2], res[3]);
}

// ---------------- launch ------------------------------------------------------------
extern "C" void kernel_launch(void* const* d_in, const int* in_sizes, int n_in,
                              void* d_out, int out_size)
{
    const float* x      = (const float*)d_in[0];
    const void*  ei     = d_in[1];
    const float* ea     = (const float*)d_in[2];
    const float* W_edge = (const float*)d_in[3];
    const float* b_edge = (const float*)d_in[4];
    const float* epsp   = (const float*)d_in[5];
    const float* W1     = (const float*)d_in[6];
    const float* b1     = (const float*)d_in[7];
    const float* g1     = (const float*)d_in[8];
    const float* beta1  = (const float*)d_in[9];
    const float* W2     = (const float*)d_in[10];
    const float* b2     = (const float*)d_in[11];
    const float* g_o    = (const float*)d_in[12];
    const float* beta_o = (const float*)d_in[13];
    float* out = (float*)d_out;

    int M = in_sizes[0] / EMB;     // 50000
    int E = in_sizes[1] / 2;       // 800000
    float invM = 1.0f / (float)M;
    int nScanBlocks = (M + SCAN_B - 1) / SCAN_B;

    zero_kernel<<<(M + 255) / 256, 256>>>(M);
    detect_kernel<<<1, 1>>>((const unsigned long long*)ei, M);
    hist_kernel<<<(E + 255) / 256, 256>>>(ei, E);
    scan1_kernel<<<nScanBlocks, SCAN_B>>>(M);
    scan2_kernel<<<1, 32>>>(nScanBlocks, M);
    scan3_kernel<<<nScanBlocks, SCAN_B>>>(M);
    scatter_kernel<<<(E + 255) / 256, 256>>>(ei, E);
    aggr_kernel<<<(M + 7) / 8, 256>>>((const float4*)x, ea,
                                      (const float4*)W_edge, (const float4*)b_edge, M);
    int gM = (M + 127) / 128;
    gemm1_kernel<<<dim3(gM, 2), 256>>>(x, W1, b1, epsp, M);
    stats1_kernel<<<(M + 255) / 256, 256>>>(M);
    finalize_kernel<<<1, 256>>>(g1, beta1, 0, invM);
    gemm2_kernel<<<gM, 256>>>(W2, b2, out, M);
    stats2_kernel<<<(M + 255) / 256, 128>>>(out, M);
    finalize_kernel<<<1, 128>>>(g_o, beta_o, 1, invM);
    bn_dropout_kernel<<<(out_size / 4 + 255) / 256, 256>>>(out, out_size);
}